// round 12
// baseline (speedup 1.0000x reference)
#include <cuda_runtime.h>
#include <cuda_bf16.h>
#include <cuda_fp16.h>
#include <cstddef>
#include <cstdint>

#define NN   50000
#define HIDD 128
#define EK   400000
#define NK   5
#define TOT  (NK*EK)
#define GG   500
#define NLAYERS 5       // l = 0..4
#define NTILES  391     // ceil(50000/128)
#define NCONVS  15
#define CAP   64        // bucket capacity per (slice,dst); deg ~ Poisson(8)

// ---------------- static device scratch ----------------
__device__ __align__(256) __half g_xh[NLAYERS][NN*HIDD];    // activations fp16 (single)
__device__ __align__(256) __half g_hmm[NK][NN*HIDD];        // dinv-prefolded GEMM results (fp16)
__device__ __align__(256) __half g_whf[NCONVS*HIDD*HIDD];   // weights fp16 (single)
__device__ int   g_bcnt[NK][NN];
__device__ int   g_bsrc[NK][NN*CAP];
__device__ float g_pool[GG*256];    // [ssum(128) | smax-bits(128)]
__device__ int   g_cnt[GG];

// ---------------- helpers ----------------
__device__ __forceinline__ uint32_t smem_u32(const void* p) {
    uint32_t a;
    asm("{ .reg .u64 t; cvta.to.shared.u64 t, %1; cvt.u32.u64 %0, t; }" : "=r"(a) : "l"(p));
    return a;
}
__device__ __forceinline__ void ldsm4(uint32_t* r, uint32_t addr) {
    asm volatile("ldmatrix.sync.aligned.m8n8.x4.shared.b16 {%0,%1,%2,%3}, [%4];"
        : "=r"(r[0]), "=r"(r[1]), "=r"(r[2]), "=r"(r[3]) : "r"(addr));
}
__device__ __forceinline__ void mma16816h(float* c, const uint32_t* a, const uint32_t* b) {
    asm volatile("mma.sync.aligned.m16n8k16.row.col.f32.f16.f16.f32 "
        "{%0,%1,%2,%3}, {%4,%5,%6,%7}, {%8,%9}, {%0,%1,%2,%3};"
        : "+f"(c[0]), "+f"(c[1]), "+f"(c[2]), "+f"(c[3])
        : "r"(a[0]), "r"(a[1]), "r"(a[2]), "r"(a[3]), "r"(b[0]), "r"(b[1]));
}
__device__ __forceinline__ void cpasync16(uint32_t dst, const void* src, int sz) {
    asm volatile("cp.async.ca.shared.global [%0], [%1], 16, %2;"
        :: "r"(dst), "l"(src), "r"(sz) : "memory");
}
#define CP_COMMIT() asm volatile("cp.async.commit_group;" ::: "memory")
#define CP_WAIT1()  asm volatile("cp.async.wait_group 1;" ::: "memory")

__device__ __forceinline__ uint32_t pack2h(__half a, __half b) {
    return (uint32_t)__half_as_ushort(a) | ((uint32_t)__half_as_ushort(b) << 16);
}
__device__ __forceinline__ void split_h(float v, __half& h, __half& lo) {
    h  = __float2half_rn(v);
    lo = __float2half_rn(v - __half2float(h));
}
// add 8 packed halves (uint4) into 8 fp32 accumulators
__device__ __forceinline__ void add8(float* s, uint4 v) {
    float2 f0 = __half22float2(*(const __half2*)&v.x);
    float2 f1 = __half22float2(*(const __half2*)&v.y);
    float2 f2 = __half22float2(*(const __half2*)&v.z);
    float2 f3 = __half22float2(*(const __half2*)&v.w);
    s[0] += f0.x; s[1] += f0.y; s[2] += f1.x; s[3] += f1.y;
    s[4] += f2.x; s[5] += f2.y; s[6] += f3.x; s[7] += f3.y;
}

// ---------------- prep: zero counters/pool + weight fp16 convert ----------------
__global__ void prep_kernel(const float* __restrict__ conv_W) {
    int i = blockIdx.x * blockDim.x + threadIdx.x;
    if (i < NK * NN) ((int*)g_bcnt)[i] = 0;
    if (i < GG*256) g_pool[i] = 0.0f;
    if (i < GG)     g_cnt[i] = 0;
    if (i < NCONVS*HIDD*HIDD) g_whf[i] = __float2half_rn(conv_W[i]);
}

// ---------------- bucket scatter ----------------
__global__ void scatter_kernel(const int* __restrict__ ei) {
    int e = blockIdx.x * blockDim.x + threadIdx.x;
    if (e >= TOT) return;
    int k   = e / EK;
    int src = ei[e];
    int dst = ei[TOT + e];
    int pos = atomicAdd(&g_bcnt[k][dst], 1);
    if (pos < CAP) g_bsrc[k][dst * CAP + pos] = src;
}

// ---------------- HMMA embedding GEMM: x0 = x @ emb_W^T + emb_b (3-pass hi/lo) ----------------
#define ESM_TOTAL 65536

__global__ __launch_bounds__(256)
void emb_mma_kernel(const float* __restrict__ x, const float* __restrict__ emb_W,
                    const float* __restrict__ emb_b, __half* __restrict__ out) {
    extern __shared__ char smem[];
    const int tid = threadIdx.x, wid = tid >> 5, lane = tid & 31;
    const int warpM = wid >> 2, warpN = wid & 3;
    const int row0 = blockIdx.x * 128;
    uint32_t sb = smem_u32(smem);
    const uint32_t sAh = sb, sAl = sb + 16384, sWh = sb + 32768, sWl = sb + 49152;

    {
        int col = tid & 31;
        #pragma unroll
        for (int it = 0; it < 16; it++) {
            int r = it * 8 + (tid >> 5);
            uint32_t off = (uint32_t)(r * 128 + (((col >> 3) ^ (r & 7)) << 4) + (col & 7) * 2);
            int grow = row0 + r;
            float av = (grow < NN) ? x[(size_t)grow * 32 + col] : 0.0f;
            __half h, lo;
            split_h(av, h, lo);
            *(__half*)(smem + off)         = h;
            *(__half*)(smem + 16384 + off) = lo;
            float wv = emb_W[(size_t)r * 32 + col];
            split_h(wv, h, lo);
            *(__half*)(smem + 32768 + off) = h;
            *(__half*)(smem + 49152 + off) = lo;
        }
    }
    __syncthreads();

    const int lr = lane & 15, lc = lane >> 4;
    float acc[4][4][4];
    #pragma unroll
    for (int i = 0; i < 4; i++)
        #pragma unroll
        for (int j = 0; j < 4; j++)
            #pragma unroll
            for (int f = 0; f < 4; f++) acc[i][j][f] = 0.0f;

    #pragma unroll
    for (int kc = 0; kc < 2; kc++) {
        uint32_t ahf[4][4], alf[4][4], whf[4][2], wlf[4][2];
        int ch = kc * 2 + lc;
        #pragma unroll
        for (int i = 0; i < 4; i++) {
            int row = warpM * 64 + i * 16 + lr;
            uint32_t roff = row * 128 + ((ch ^ (row & 7)) << 4);
            ldsm4(ahf[i], sAh + roff);
            ldsm4(alf[i], sAl + roff);
        }
        #pragma unroll
        for (int j2 = 0; j2 < 2; j2++) {
            int row = warpN * 32 + j2 * 16 + lr;
            uint32_t roff = row * 128 + ((ch ^ (row & 7)) << 4);
            uint32_t t[4];
            ldsm4(t, sWh + roff);
            whf[j2*2+0][0] = t[0]; whf[j2*2+0][1] = t[2];
            whf[j2*2+1][0] = t[1]; whf[j2*2+1][1] = t[3];
            ldsm4(t, sWl + roff);
            wlf[j2*2+0][0] = t[0]; wlf[j2*2+0][1] = t[2];
            wlf[j2*2+1][0] = t[1]; wlf[j2*2+1][1] = t[3];
        }
        #pragma unroll
        for (int i = 0; i < 4; i++)
            #pragma unroll
            for (int j = 0; j < 4; j++) {
                mma16816h(acc[i][j], ahf[i], whf[j]);
                mma16816h(acc[i][j], alf[i], whf[j]);
                mma16816h(acc[i][j], ahf[i], wlf[j]);
            }
    }

    int rbase = row0 + warpM * 64;
    #pragma unroll
    for (int i = 0; i < 4; i++) {
        int r0 = rbase + i * 16 + (lane >> 2);
        int r8 = r0 + 8;
        #pragma unroll
        for (int j = 0; j < 4; j++) {
            int c0 = warpN * 32 + j * 8 + (lane & 3) * 2;
            float2 bv = *(const float2*)(emb_b + c0);
            if (r0 < NN)
                *(__half2*)(out + (size_t)r0 * HIDD + c0) =
                    __floats2half2_rn(acc[i][j][0] + bv.x, acc[i][j][1] + bv.y);
            if (r8 < NN)
                *(__half2*)(out + (size_t)r8 * HIDD + c0) =
                    __floats2half2_rn(acc[i][j][2] + bv.x, acc[i][j][3] + bv.y);
        }
    }
}

// ---------------- HMMA fp16 1-pass GEMM: hmm[kk] = dinv[kk] * (x[l-kk] @ W[ci]^T) ----------------
#define SMEM_TOTAL (3*32768)

__device__ __forceinline__ void load_tile_async(uint32_t sbase, const __half* __restrict__ g,
                                                int row0, int maxrow) {
    int tid = threadIdx.x;
    #pragma unroll
    for (int i = 0; i < 8; i++) {
        int q = tid + i * 256;
        int r = q >> 4;
        int c = q & 15;
        uint32_t off = sbase + r * 256 + ((c ^ (r & 7)) << 4);
        int grow = row0 + r;
        int ok = (grow < maxrow);
        const void* src = g + (size_t)(ok ? grow : 0) * HIDD + c * 8;
        cpasync16(off, src, ok ? 16 : 0);
    }
}

__global__ __launch_bounds__(256, 1)
void mma_gemm_kernel(int l) {
    extern __shared__ char smem[];
    const int tid = threadIdx.x, wid = tid >> 5, lane = tid & 31;
    const int warpM = wid >> 2, warpN = wid & 3;
    const int kk = blockIdx.y;
    const int ci = l * (l + 1) / 2 + kk;
    const __half* Ax = g_xh[l - kk];
    const __half* Wf = g_whf + (size_t)ci * HIDD * HIDD;
    const int* bcnt = g_bcnt[kk];
    __half* outp = g_hmm[kk];
    uint32_t sb = smem_u32(smem);
    const uint32_t sB  = sb;
    const uint32_t sA0 = sb + 32768, sA1 = sb + 65536;

    load_tile_async(sB, Wf, 0, 1 << 30);
    int mt = blockIdx.x;
    load_tile_async(sA0, Ax, mt * 128, NN);
    CP_COMMIT();

    const int lr = lane & 15, lc = lane >> 4;
    int buf = 0;
    for (; mt < NTILES; mt += gridDim.x) {
        int nmt = mt + gridDim.x;
        uint32_t aCur = buf ? sA1 : sA0;
        uint32_t aNxt = buf ? sA0 : sA1;
        if (nmt < NTILES)
            load_tile_async(aNxt, Ax, nmt * 128, NN);
        CP_COMMIT();
        CP_WAIT1();
        __syncthreads();

        float acc[4][4][4];
        #pragma unroll
        for (int i = 0; i < 4; i++)
            #pragma unroll
            for (int j = 0; j < 4; j++)
                #pragma unroll
                for (int f = 0; f < 4; f++) acc[i][j][f] = 0.0f;

        #pragma unroll
        for (int kc = 0; kc < 8; kc++) {
            uint32_t af[4][4], bf[4][2];
            int ch = kc * 2 + lc;
            #pragma unroll
            for (int i = 0; i < 4; i++) {
                int row = warpM * 64 + i * 16 + lr;
                ldsm4(af[i], aCur + row * 256 + ((ch ^ (row & 7)) << 4));
            }
            #pragma unroll
            for (int j2 = 0; j2 < 2; j2++) {
                int row = warpN * 32 + j2 * 16 + lr;
                uint32_t t[4];
                ldsm4(t, sB + row * 256 + ((ch ^ (row & 7)) << 4));
                bf[j2*2+0][0] = t[0]; bf[j2*2+0][1] = t[2];
                bf[j2*2+1][0] = t[1]; bf[j2*2+1][1] = t[3];
            }
            #pragma unroll
            for (int i = 0; i < 4; i++)
                #pragma unroll
                for (int j = 0; j < 4; j++)
                    mma16816h(acc[i][j], af[i], bf[j]);
        }

        // epilogue: inline dinv prefold + fp16 store
        int rbase = mt * 128 + warpM * 64;
        #pragma unroll
        for (int i = 0; i < 4; i++) {
            int r0 = rbase + i * 16 + (lane >> 2);
            int r8 = r0 + 8;
            float dv0 = (r0 < NN) ? rsqrtf((float)bcnt[r0] + 1.0f) : 0.0f;
            float dv8 = (r8 < NN) ? rsqrtf((float)bcnt[r8] + 1.0f) : 0.0f;
            #pragma unroll
            for (int j = 0; j < 4; j++) {
                int c0 = warpN * 32 + j * 8 + (lane & 3) * 2;
                if (r0 < NN)
                    *(__half2*)(outp + (size_t)r0 * HIDD + c0) =
                        __floats2half2_rn(acc[i][j][0] * dv0, acc[i][j][1] * dv0);
                if (r8 < NN)
                    *(__half2*)(outp + (size_t)r8 * HIDD + c0) =
                        __floats2half2_rn(acc[i][j][2] * dv8, acc[i][j][3] * dv8);
            }
        }
        __syncthreads();
        buf ^= 1;
    }
}

// ---------------- fused aggregation v2: warp per dst, half-warp per edge, LDG.128 ----------------
// out[d] = relu( Σ_kk s·dinv[kk][d]·(hmm'[d] + Σ_src hmm'[src]) + s·b )  (hmm' dinv-prefolded)
// lane = hw*16 + c16 : hw = edge slot (0/1), c16 = 16B feature chunk (8 halves)
__global__ __launch_bounds__(256)
void agg_kernel(int l, const float* __restrict__ conv_b, const int* __restrict__ batch) {
    int gw   = (blockIdx.x * blockDim.x + threadIdx.x) >> 5;
    int lane = threadIdx.x & 31;
    if (gw >= NN) return;
    const int d   = gw;
    const int hw  = lane >> 4;
    const int c16 = lane & 15;
    const int base_ci = l * (l + 1) / 2;

    float acc[8];
    #pragma unroll
    for (int i = 0; i < 8; i++) acc[i] = 0.0f;

    for (int kk = 0; kk <= l; kk++) {
        const float s = 1.0f / (float)(kk + 1);
        const int cdeg = g_bcnt[kk][d];
        const float dinvd = rsqrtf((float)cdeg + 1.0f);
        const __half* hmm = g_hmm[kk];

        float sum[8];
        #pragma unroll
        for (int i = 0; i < 8; i++) sum[i] = 0.0f;

        // self row (exact edge-equivalent after prefold): half-warp 0 only
        if (hw == 0) {
            uint4 sv = *(const uint4*)(hmm + (size_t)d * HIDD + c16 * 8);
            add8(sum, sv);
        }

        const int c = min(cdeg, CAP);
        const int* bk = &g_bsrc[kk][d * CAP];
        for (int e0 = 0; e0 < c; e0 += 32) {
            int e = e0 + lane;
            int srcI = (e < c) ? bk[e] : 0;
            int m = min(32, c - e0);
            int j = 0;
            for (; j + 4 <= m; j += 4) {          // 4 edges per iter, 2 LDG.128 in flight
                int sA = __shfl_sync(0xffffffffu, srcI, j + hw);
                int sB2 = __shfl_sync(0xffffffffu, srcI, j + 2 + hw);
                uint4 vA = *(const uint4*)(hmm + (size_t)sA * HIDD + c16 * 8);
                uint4 vB = *(const uint4*)(hmm + (size_t)sB2 * HIDD + c16 * 8);
                add8(sum, vA);
                add8(sum, vB);
            }
            for (; j < m; j += 2) {               // tail: clamp shfl index, predicate add
                int idx = j + hw;
                int sA = __shfl_sync(0xffffffffu, srcI, min(idx, m - 1));
                if (idx < m) {
                    uint4 vA = *(const uint4*)(hmm + (size_t)sA * HIDD + c16 * 8);
                    add8(sum, vA);
                }
            }
        }

        const float sdv = s * dinvd;
        #pragma unroll
        for (int i = 0; i < 8; i++) acc[i] = fmaf(sdv, sum[i], acc[i]);

        if (hw == 0) {                            // bias once
            const float* bp = conv_b + (size_t)(base_ci + kk) * HIDD + c16 * 8;
            float4 b0 = *(const float4*)bp;
            float4 b1 = *(const float4*)(bp + 4);
            acc[0] = fmaf(s, b0.x, acc[0]); acc[1] = fmaf(s, b0.y, acc[1]);
            acc[2] = fmaf(s, b0.z, acc[2]); acc[3] = fmaf(s, b0.w, acc[3]);
            acc[4] = fmaf(s, b1.x, acc[4]); acc[5] = fmaf(s, b1.y, acc[5]);
            acc[6] = fmaf(s, b1.z, acc[6]); acc[7] = fmaf(s, b1.w, acc[7]);
        }
    }

    // combine half-warps, relu
    #pragma unroll
    for (int i = 0; i < 8; i++) {
        acc[i] += __shfl_xor_sync(0xffffffffu, acc[i], 16);
        acc[i] = fmaxf(acc[i], 0.0f);
    }

    if (hw == 0) {
        if (l == NLAYERS - 1) {
            int g = batch[d];
            float* ss = &g_pool[(size_t)g * 256];
            int*   sm = (int*)&g_pool[(size_t)g * 256 + 128];
            #pragma unroll
            for (int i = 0; i < 8; i++) {
                atomicAdd(&ss[c16 * 8 + i], acc[i]);
                atomicMax(&sm[c16 * 8 + i], __float_as_int(acc[i]));
            }
            if (lane == 0) atomicAdd(&g_cnt[g], 1);
        } else {
            uint4 ph;
            ph.x = pack2h(__float2half_rn(acc[0]), __float2half_rn(acc[1]));
            ph.y = pack2h(__float2half_rn(acc[2]), __float2half_rn(acc[3]));
            ph.z = pack2h(__float2half_rn(acc[4]), __float2half_rn(acc[5]));
            ph.w = pack2h(__float2half_rn(acc[6]), __float2half_rn(acc[7]));
            *(uint4*)(g_xh[l + 1] + (size_t)d * HIDD + c16 * 8) = ph;
        }
    }
}

// ---------------- readout: [ssum|smax|smean] @ r1^T -> leaky -> @ r2^T ----------------
__global__ __launch_bounds__(384)
void readout_kernel(const float* __restrict__ r1W, const float* __restrict__ r1b,
                    const float* __restrict__ r2W, const float* __restrict__ r2b,
                    float* __restrict__ out) {
    int g = blockIdx.x, tid = threadIdx.x;
    __shared__ float sp[384];
    __shared__ float sh[192];
    if (tid < 256) sp[tid] = g_pool[(size_t)g * 256 + tid];
    __syncthreads();
    if (tid < 128) {
        float c = fmaxf((float)g_cnt[g], 1.0f);
        sp[256 + tid] = sp[tid] / c;       // smean
    }
    __syncthreads();
    if (tid < 192) {
        float a = r1b[tid];
        const float4* w = (const float4*)&r1W[(size_t)tid * 384];
        #pragma unroll 8
        for (int j = 0; j < 96; j++) {
            float4 wv = w[j];
            float4 pv = *(const float4*)&sp[j*4];
            a = fmaf(wv.x, pv.x, a); a = fmaf(wv.y, pv.y, a);
            a = fmaf(wv.z, pv.z, a); a = fmaf(wv.w, pv.w, a);
        }
        sh[tid] = (a >= 0.0f) ? a : 0.01f * a;
    }
    __syncthreads();
    if (tid < 10) {
        float a = r2b[tid];
        const float4* w = (const float4*)&r2W[(size_t)tid * 192];
        #pragma unroll
        for (int j = 0; j < 48; j++) {
            float4 wv = w[j];
            float4 pv = *(const float4*)&sh[j*4];
            a = fmaf(wv.x, pv.x, a); a = fmaf(wv.y, pv.y, a);
            a = fmaf(wv.z, pv.z, a); a = fmaf(wv.w, pv.w, a);
        }
        out[g * 10 + tid] = a;
    }
}

// ---------------- launch ----------------
extern "C" void kernel_launch(void* const* d_in, const int* in_sizes, int n_in,
                              void* d_out, int out_size) {
    const float* x      = (const float*)d_in[0];
    const int*   ei     = (const int*)d_in[1];
    const int*   batch  = (const int*)d_in[3];
    const float* emb_W  = (const float*)d_in[4];
    const float* emb_b  = (const float*)d_in[5];
    const float* conv_W = (const float*)d_in[6];
    const float* conv_b = (const float*)d_in[7];
    const float* r1_W   = (const float*)d_in[8];
    const float* r1_b   = (const float*)d_in[9];
    const float* r2_W   = (const float*)d_in[10];
    const float* r2_b   = (const float*)d_in[11];
    float* out = (float*)d_out;

    cudaFuncSetAttribute(mma_gemm_kernel, cudaFuncAttributeMaxDynamicSharedMemorySize, SMEM_TOTAL);
    cudaFuncSetAttribute(emb_mma_kernel, cudaFuncAttributeMaxDynamicSharedMemorySize, ESM_TOTAL);

    __half* x0;
    {
        void* p;
        cudaGetSymbolAddress(&p, g_xh); x0 = (__half*)p;
    }

    // 1. prep: zero bucket counters/pool + fp16 weight convert
    prep_kernel<<<(NK * NN + 255) / 256, 256>>>(conv_W);
    // 2. bucket scatter (dinv now computed inline from counts)
    scatter_kernel<<<(TOT + 255) / 256, 256>>>(ei);
    // 3. embedding via HMMA (3-pass hi/lo, near-exact) -> fp16 x0
    emb_mma_kernel<<<NTILES, 256, ESM_TOTAL>>>(x, emb_W, emb_b, x0);

    // 4. layers: HMMA fp16 1-pass batched GEMMs + fused aggregation (last fuses pooling)
    static const int gx[NLAYERS] = {131, 66, 49, 36, 28};
    for (int l = 0; l < NLAYERS; l++) {
        dim3 grid(gx[l], l + 1);
        mma_gemm_kernel<<<grid, 256, SMEM_TOTAL>>>(l);
        agg_kernel<<<(NN * 32 + 255) / 256, 256>>>(l, conv_b, batch);
    }

    // 5. readout (smean folded in)
    readout_kernel<<<GG, 384>>>(r1_W, r1_b, r2_W, r2_b, out);
}